// round 1
// baseline (speedup 1.0000x reference)
#include <cuda_runtime.h>
#include <math.h>

#define NPTS   2048
#define NGAB   2
#define IMG_H  512
#define IMG_W  512
#define HW     (IMG_H * IMG_W)
#define RENDER_SZ (3 * HW)
#define ALPHA_THRESH (1.0f / 255.0f)

struct GPt {
    float x, y;
    float ca, cb, cc;
    float op;
    float r, g, b;
    float fx0, fy0, fx1, fy1;
    float w0, w1;
    int x0, x1, y0, y1;   // inclusive pixel bbox; x1 < x0 => skip
};

__device__ GPt g_pts[NPTS];

__device__ __forceinline__ float sigmoidf_(float v) {
    return 1.0f / (1.0f + __expf(-v));
}

// Zero the render region of d_out, preprocess all points, write radii/visibility.
__global__ void prep_kernel(const float* __restrict__ xyz,
                            const float* __restrict__ cov2d,
                            const float* __restrict__ fdc,
                            const float* __restrict__ opac,
                            const float* __restrict__ gfreq,
                            const float* __restrict__ gwt,
                            float* __restrict__ out, int out_size) {
    int i = blockIdx.x * blockDim.x + threadIdx.x;
    if (i < RENDER_SZ) out[i] = 0.0f;
    if (i >= NPTS) return;

    float sxx = cov2d[3 * i + 0] + 0.5f;
    float sxy = cov2d[3 * i + 1];
    float syy = cov2d[3 * i + 2] + 0.5f;
    float det = sxx * syy - sxy * sxy;
    bool valid = det > 1e-8f;
    float det_s = valid ? det : 1.0f;

    float ca = syy / det_s;
    float cb = -sxy / det_s;
    float cc = sxx / det_s;

    float mid = 0.5f * (sxx + syy);
    float lam = mid + sqrtf(fmaxf(mid * mid - det, 0.1f));
    int radii = valid ? (int)ceilf(3.0f * sqrtf(lam)) : 0;

    // Secondary outputs (guarded: packing convention = render || radii || visibility, float)
    if (out_size >= RENDER_SZ + NPTS)
        out[RENDER_SZ + i] = (float)radii;
    if (out_size >= RENDER_SZ + 2 * NPTS)
        out[RENDER_SZ + NPTS + i] = (radii > 0) ? 1.0f : 0.0f;

    GPt p;
    p.x = xyz[2 * i + 0];
    p.y = xyz[2 * i + 1];
    p.ca = ca; p.cb = cb; p.cc = cc;
    float op = opac[i];
    p.op = op;
    p.r = sigmoidf_(fdc[3 * i + 0]);
    p.g = sigmoidf_(fdc[3 * i + 1]);
    p.b = sigmoidf_(fdc[3 * i + 2]);
    // gabor_freqs: (N*G, 2) -> (n, g, 2): flat (i*NGAB + j)*2 + k
    p.fx0 = __expf(gfreq[(i * NGAB + 0) * 2 + 0]);
    p.fy0 = __expf(gfreq[(i * NGAB + 0) * 2 + 1]);
    p.fx1 = __expf(gfreq[(i * NGAB + 1) * 2 + 0]);
    p.fy1 = __expf(gfreq[(i * NGAB + 1) * 2 + 1]);
    p.w0 = sigmoidf_(gwt[i * NGAB + 0]);
    p.w1 = sigmoidf_(gwt[i * NGAB + 1]);

    // Conservative support bbox: alpha >= 1/255 requires sigma <= ln(255*op).
    // Max |dx| on that level set = sqrt(2*T*sxx) (conic = Sigma^{-1}); +1px slop.
    float T = __logf(fmaxf(op, 1e-30f) * 255.0f);
    p.x0 = 1; p.x1 = 0; p.y0 = 1; p.y1 = 0;
    if (valid && T > 0.0f) {
        float dxm = sqrtf(2.0f * T * sxx) + 1.0f;
        float dym = sqrtf(2.0f * T * syy) + 1.0f;
        int x0 = max(0, (int)floorf(p.x - dxm - 0.5f));
        int x1 = min(IMG_W - 1, (int)ceilf(p.x + dxm - 0.5f));
        int y0 = max(0, (int)floorf(p.y - dym - 0.5f));
        int y1 = min(IMG_H - 1, (int)ceilf(p.y + dym - 0.5f));
        if (x0 <= x1 && y0 <= y1) {
            p.x0 = x0; p.x1 = x1; p.y0 = y0; p.y1 = y1;
        }
    }
    g_pts[i] = p;
}

// One warp per Gaussian; scatter into d_out with atomicAdd (RED path).
__global__ void splat_kernel(float* __restrict__ out) {
    int g = (blockIdx.x * blockDim.x + threadIdx.x) >> 5;
    int lane = threadIdx.x & 31;
    if (g >= NPTS) return;

    GPt p = g_pts[g];
    int bw = p.x1 - p.x0 + 1;
    int bh = p.y1 - p.y0 + 1;
    if (bw <= 0 || bh <= 0) return;
    int npix = bw * bh;

    for (int t = lane; t < npix; t += 32) {
        int px = p.x0 + (t % bw);
        int py = p.y0 + (t / bw);
        float dx = ((float)px + 0.5f) - p.x;
        float dy = ((float)py + 0.5f) - p.y;
        float sigma = 0.5f * (p.ca * dx * dx + p.cc * dy * dy) + p.cb * (dx * dy);
        float alpha = fminf(p.op * __expf(-sigma), 0.999f);
        if (alpha < ALPHA_THRESH) continue;   // exact reference threshold
        float arg0 = p.fx0 * dx + p.fy0 * dy;
        float arg1 = p.fx1 * dx + p.fy1 * dy;
        float mod = 1.0f + p.w0 * __cosf(arg0) + p.w1 * __cosf(arg1);
        float wgt = alpha * mod;
        int pix = py * IMG_W + px;
        atomicAdd(&out[pix],            wgt * p.r);
        atomicAdd(&out[HW + pix],       wgt * p.g);
        atomicAdd(&out[2 * HW + pix],   wgt * p.b);
    }
}

// Final clip(out, 0, 1) on the render region.
__global__ void clamp_kernel(float* __restrict__ out) {
    int i = blockIdx.x * blockDim.x + threadIdx.x;
    if (i < RENDER_SZ)
        out[i] = fminf(fmaxf(out[i], 0.0f), 1.0f);
}

extern "C" void kernel_launch(void* const* d_in, const int* in_sizes, int n_in,
                              void* d_out, int out_size) {
    const float* xyz   = (const float*)d_in[0];
    const float* cov2d = (const float*)d_in[1];
    const float* fdc   = (const float*)d_in[2];
    const float* opac  = (const float*)d_in[3];
    const float* gfreq = (const float*)d_in[4];
    const float* gwt   = (const float*)d_in[5];
    // d_in[6] = background (unused by reference render), d_in[7]=H, d_in[8]=W (fixed 512)
    float* out = (float*)d_out;

    const int threads = 256;
    int prep_blocks = (RENDER_SZ + threads - 1) / threads;  // covers zeroing + 2048 points
    prep_kernel<<<prep_blocks, threads>>>(xyz, cov2d, fdc, opac, gfreq, gwt, out, out_size);

    int splat_blocks = (NPTS * 32 + threads - 1) / threads; // one warp per point
    splat_kernel<<<splat_blocks, threads>>>(out);

    clamp_kernel<<<prep_blocks, threads>>>(out);
}

// round 2
// speedup vs baseline: 1.3780x; 1.3780x over previous
#include <cuda_runtime.h>
#include <math.h>

#define NPTS   2048
#define NGAB   2
#define IMG_H  512
#define IMG_W  512
#define HW     (IMG_H * IMG_W)
#define RENDER_SZ (3 * HW)
#define ALPHA_THRESH (1.0f / 255.0f)

// Persistent accumulation buffer. Zero at module load; the finish kernel
// re-zeroes it after consuming, so every kernel_launch sees zeros.
__device__ float g_accum[RENDER_SZ];

__device__ __forceinline__ float sigmoidf_(float v) {
    return 1.0f / (1.0f + __expf(-v));
}

// One warp per Gaussian. All lanes redundantly run the (tiny) per-point
// preprocessing from broadcast loads, then cooperatively splat the bbox
// with the exact reference alpha threshold applied per pixel.
__global__ void splat_kernel(const float* __restrict__ xyz,
                             const float* __restrict__ cov2d,
                             const float* __restrict__ fdc,
                             const float* __restrict__ opac,
                             const float* __restrict__ gfreq,
                             const float* __restrict__ gwt,
                             float* __restrict__ out, int out_size) {
    int g    = (blockIdx.x * blockDim.x + threadIdx.x) >> 5;
    int lane = threadIdx.x & 31;
    if (g >= NPTS) return;

    // ---- per-point prep (broadcast loads; identical in all lanes) ----
    float sxx = cov2d[3 * g + 0] + 0.5f;
    float sxy = cov2d[3 * g + 1];
    float syy = cov2d[3 * g + 2] + 0.5f;
    float det = sxx * syy - sxy * sxy;
    bool valid = det > 1e-8f;
    float det_s = valid ? det : 1.0f;
    float ca =  syy / det_s;
    float cb = -sxy / det_s;
    float cc =  sxx / det_s;

    float mid = 0.5f * (sxx + syy);
    float lam = mid + sqrtf(fmaxf(mid * mid - det, 0.1f));
    int radii = valid ? (int)ceilf(3.0f * sqrtf(lam)) : 0;

    if (lane == 0) {
        if (out_size >= RENDER_SZ + NPTS)
            out[RENDER_SZ + g] = (float)radii;
        if (out_size >= RENDER_SZ + 2 * NPTS)
            out[RENDER_SZ + NPTS + g] = (radii > 0) ? 1.0f : 0.0f;
    }

    float x = xyz[2 * g + 0];
    float y = xyz[2 * g + 1];
    float op = opac[g];
    float cr = sigmoidf_(fdc[3 * g + 0]);
    float cg = sigmoidf_(fdc[3 * g + 1]);
    float cbl = sigmoidf_(fdc[3 * g + 2]);
    float fx0 = __expf(gfreq[(g * NGAB + 0) * 2 + 0]);
    float fy0 = __expf(gfreq[(g * NGAB + 0) * 2 + 1]);
    float fx1 = __expf(gfreq[(g * NGAB + 1) * 2 + 0]);
    float fy1 = __expf(gfreq[(g * NGAB + 1) * 2 + 1]);
    float w0 = sigmoidf_(gwt[g * NGAB + 0]);
    float w1 = sigmoidf_(gwt[g * NGAB + 1]);

    // Conservative support bbox: alpha >= 1/255 requires sigma <= ln(255*op).
    // Max |dx| on that level set = sqrt(2*T*sxx) (conic = Sigma^{-1}); +1px slop.
    float T = __logf(fmaxf(op, 1e-30f) * 255.0f);
    if (!valid || T <= 0.0f) return;
    float dxm = sqrtf(2.0f * T * sxx) + 1.0f;
    float dym = sqrtf(2.0f * T * syy) + 1.0f;
    int x0 = max(0, (int)floorf(x - dxm - 0.5f));
    int x1 = min(IMG_W - 1, (int)ceilf(x + dxm - 0.5f));
    int y0 = max(0, (int)floorf(y - dym - 0.5f));
    int y1 = min(IMG_H - 1, (int)ceilf(y + dym - 0.5f));
    int bw = x1 - x0 + 1;
    int bh = y1 - y0 + 1;
    if (bw <= 0 || bh <= 0) return;
    int npix = bw * bh;

    for (int t = lane; t < npix; t += 32) {
        int px = x0 + (t % bw);
        int py = y0 + (t / bw);
        float dx = ((float)px + 0.5f) - x;
        float dy = ((float)py + 0.5f) - y;
        float sigma = 0.5f * (ca * dx * dx + cc * dy * dy) + cb * (dx * dy);
        float alpha = fminf(op * __expf(-sigma), 0.999f);
        if (alpha < ALPHA_THRESH) continue;   // exact reference threshold
        float arg0 = fx0 * dx + fy0 * dy;
        float arg1 = fx1 * dx + fy1 * dy;
        float mod = 1.0f + w0 * __cosf(arg0) + w1 * __cosf(arg1);
        float wgt = alpha * mod;
        int pix = py * IMG_W + px;
        atomicAdd(&g_accum[pix],          wgt * cr);
        atomicAdd(&g_accum[HW + pix],     wgt * cg);
        atomicAdd(&g_accum[2 * HW + pix], wgt * cbl);
    }
}

// Read accum -> clamp -> write d_out, and re-zero accum for the next launch.
__global__ void finish_kernel(float* __restrict__ out) {
    int i = blockIdx.x * blockDim.x + threadIdx.x;   // float4 index
    if (i >= RENDER_SZ / 4) return;
    float4* acc4 = reinterpret_cast<float4*>(g_accum);
    float4* out4 = reinterpret_cast<float4*>(out);
    float4 v = acc4[i];
    v.x = fminf(fmaxf(v.x, 0.0f), 1.0f);
    v.y = fminf(fmaxf(v.y, 0.0f), 1.0f);
    v.z = fminf(fmaxf(v.z, 0.0f), 1.0f);
    v.w = fminf(fmaxf(v.w, 0.0f), 1.0f);
    out4[i] = v;
    acc4[i] = make_float4(0.0f, 0.0f, 0.0f, 0.0f);
}

extern "C" void kernel_launch(void* const* d_in, const int* in_sizes, int n_in,
                              void* d_out, int out_size) {
    const float* xyz   = (const float*)d_in[0];
    const float* cov2d = (const float*)d_in[1];
    const float* fdc   = (const float*)d_in[2];
    const float* opac  = (const float*)d_in[3];
    const float* gfreq = (const float*)d_in[4];
    const float* gwt   = (const float*)d_in[5];
    float* out = (float*)d_out;

    const int threads = 256;
    int splat_blocks = (NPTS * 32) / threads;          // 256 blocks, 1 warp/point
    splat_kernel<<<splat_blocks, threads>>>(xyz, cov2d, fdc, opac, gfreq, gwt, out, out_size);

    int fin_blocks = (RENDER_SZ / 4 + threads - 1) / threads;  // 768 blocks
    finish_kernel<<<fin_blocks, threads>>>(out);
}